// round 17
// baseline (speedup 1.0000x reference)
#include <cuda_runtime.h>
#include <cuda_bf16.h>
#include <cstdint>

// MK_MMDLoss R16: R15 with re-shaped warp tiling for 2x warps/SMSP.
//  - CTA: 512 threads, 16 warps in 8(M) x 2(N); warp tile 16x64 -> acc = 32
//    regs/thread -> 64-reg budget -> 1024 threads/SM resident (8 warps/SMSP,
//    was 4). Latency-hiding is the measured bottleneck (tensor rate scaled
//    ~linearly with warps across R5->R15).
//  - Same 3-stage cp.async pipeline, fused prep & finalize, analytic diagonal.

#define NR    4096
#define CD    256
#define HWD   1024
#define BM    128
#define NTILE (NR / BM)     // 32
#define NSYM  (NTILE * (NTILE + 1) / 2)   // 528
#define NFULL (NTILE * NTILE)             // 1024
#define NBLK  (2 * NSYM + NFULL)          // 2080
#define NTHR  512
#define KCH   64             // K chunk (bf16 elems)
#define NCHK  (CD / KCH)     // 4
#define NSTG  3              // pipeline stages
#define ROWB  144            // smem row bytes: 128 + 16 pad (conflict-free ldmatrix)
#define ATILE (BM * ROWB)    // 18432
#define STG   (2 * ATILE)    // 36864 per stage (A+B)
#define SM_RED (NSTG * STG)  // 110592
#define SM_TOT (SM_RED + 128)

#define EXP2_CUT (-24.0f)    // drop exp2 terms < 2^-24 ~ 6e-8

__device__ __align__(16) __nv_bfloat16 g_xb[NR * CD];
__device__ __align__(16) __nv_bfloat16 g_yb[NR * CD];
__device__ float  g_x2[NR];
__device__ float  g_y2[NR];
__device__ double g_acc;
__device__ unsigned int g_done = 0;

__device__ __forceinline__ uint32_t smem_u32(const void* p) {
    uint32_t a;
    asm("{ .reg .u64 t; cvta.to.shared.u64 t, %1; cvt.u32.u64 %0, t; }" : "=r"(a) : "l"(p));
    return a;
}
__device__ __forceinline__ void cp16(uint32_t dst, const void* src) {
    asm volatile("cp.async.cg.shared.global [%0], [%1], 16;" :: "r"(dst), "l"(src));
}
__device__ __forceinline__ void cp_commit() {
    asm volatile("cp.async.commit_group;");
}
__device__ __forceinline__ void cp_wait1() {
    asm volatile("cp.async.wait_group 1;" ::: "memory");
}
__device__ __forceinline__ void cp_wait0() {
    asm volatile("cp.async.wait_group 0;" ::: "memory");
}
__device__ __forceinline__ void ldsm4(uint32_t* d, uint32_t addr) {
    asm volatile("ldmatrix.sync.aligned.m8n8.x4.shared.b16 {%0,%1,%2,%3}, [%4];"
                 : "=r"(d[0]), "=r"(d[1]), "=r"(d[2]), "=r"(d[3]) : "r"(addr));
}
__device__ __forceinline__ void mma_bf16(float* c, const uint32_t* a,
                                         uint32_t b0, uint32_t b1) {
    asm volatile(
        "mma.sync.aligned.m16n8k16.row.col.f32.bf16.bf16.f32 "
        "{%0,%1,%2,%3}, {%4,%5,%6,%7}, {%8,%9}, {%0,%1,%2,%3};"
        : "+f"(c[0]), "+f"(c[1]), "+f"(c[2]), "+f"(c[3])
        : "r"(a[0]), "r"(a[1]), "r"(a[2]), "r"(a[3]), "r"(b0), "r"(b1));
}

// 5-term Gaussian mix. nb[k] = -bet[k]*log2(e), bets descending.
__device__ __forceinline__ float expmix(float d, const float* nb) {
    float s = exp2f(nb[4] * d) + exp2f(nb[3] * d);
    float u2 = nb[2] * d;
    if (u2 > EXP2_CUT) {
        s += exp2f(u2);
        float u1 = nb[1] * d;
        if (u1 > EXP2_CUT) {
            s += exp2f(u1);
            float u0 = nb[0] * d;
            if (u0 > EXP2_CUT) s += exp2f(u0);
        }
    }
    return s;
}

template <bool DIAG>
__device__ __forceinline__ float epilogue(const float acc[8][4],
                                          int rowA0, int rowB0, int wm, int wn,
                                          int lane, const float* a2,
                                          const float* b2, const float* nb) {
    int g = lane >> 2, t4 = lane & 3;
    float part = 0.f;
    int r0 = rowA0 + wm * 16 + g;
    float a2lo = __ldg(a2 + r0);
    float a2hi = __ldg(a2 + r0 + 8);
#pragma unroll
    for (int nt = 0; nt < 8; ++nt) {
        int c0 = rowB0 + wn * 64 + nt * 8 + t4 * 2;
        float b2e[2] = { __ldg(b2 + c0), __ldg(b2 + c0 + 1) };
#pragma unroll
        for (int e = 0; e < 4; ++e) {
            if (DIAG) {
                int grow = (e < 2) ? r0 : r0 + 8;
                int gcol = c0 + (e & 1);
                if (grow == gcol) continue;   // diag added analytically
            }
            float a2v = (e < 2) ? a2lo : a2hi;
            float d = fmaxf(fmaf(-2.0f, acc[nt][e], a2v + b2e[e & 1]), 0.f);
            part += expmix(d, nb);
        }
    }
    return part;
}

// ---------------- fused prep: convert (z<8) + row norms (z==8) ----------------
__global__ void mmd_prep_kernel(const float* __restrict__ x,
                                const float* __restrict__ y) {
    __shared__ float tile[32][33];
    int tx = threadIdx.x, ty = threadIdx.y;  // (32, 8)
    int tid = ty * 32 + tx;
    int z = blockIdx.z;

    if (z == 8) {
        if (blockIdx.y != 0) return;
        int r = blockIdx.x * 256 + tid;      // 0..8191
        if (r == 0) g_acc = 0.0;
        int arr = r >> 12;
        int row = r & 4095;
        const float* p = arr ? y : x;
        int b  = row >> 10;
        int hw = row & 1023;
        const float* base = p + (size_t)b * (CD * HWD) + hw;
        float s = 0.f;
#pragma unroll 8
        for (int c = 0; c < CD; ++c) {
            float v = base[(size_t)c * HWD];
            s = fmaf(v, v, s);
        }
        (arr ? g_y2 : g_x2)[row] = s;
        return;
    }

    int hwb = blockIdx.x * 32;
    int cb  = blockIdx.y * 32;
    int b   = z & 3;
    const float* src = (z >> 2) ? y : x;
    __nv_bfloat16* dst = (z >> 2) ? g_yb : g_xb;
    const float* s = src + (size_t)b * (CD * HWD) + hwb + tx;
#pragma unroll
    for (int i = 0; i < 4; ++i) {
        int c = cb + ty + i * 8;
        tile[ty + i * 8][tx] = s[(size_t)c * HWD];
    }
    __syncthreads();
#pragma unroll
    for (int i = 0; i < 4; ++i) {
        int hwl = ty + i * 8;
        int r = b * HWD + hwb + hwl;
        dst[(size_t)r * CD + cb + tx] = __float2bfloat16(tile[tx][hwl]);
    }
}

// ---------------- merged main: 2080 blocks = xx(528) + yy(528) + xy(1024) ----------------
__global__ void __launch_bounds__(NTHR, 2)
mmd_mma_kernel(const float* __restrict__ sig, float* __restrict__ out) {
    extern __shared__ __align__(128) char smem[];
    int tid = threadIdx.x, lane = tid & 31, wid = tid >> 5;

    int bidx = blockIdx.x;
    int mode, idx;
    if (bidx < NSYM)            { mode = 0; idx = bidx; }
    else if (bidx < 2 * NSYM)   { mode = 1; idx = bidx - NSYM; }
    else                        { mode = 2; idx = bidx - 2 * NSYM; }

    const __nv_bfloat16 *Ag, *Bg;
    const float *a2, *b2;
    double weight;
    int sym;
    if (mode == 0)      { Ag = g_xb; Bg = g_xb; a2 = g_x2; b2 = g_x2; weight =  1.0; sym = 1; }
    else if (mode == 1) { Ag = g_yb; Bg = g_yb; a2 = g_y2; b2 = g_y2; weight =  1.0; sym = 1; }
    else                { Ag = g_xb; Bg = g_yb; a2 = g_x2; b2 = g_y2; weight = -2.0; sym = 0; }

    int ti, tj;
    if (sym) {
        int b = idx; ti = 0;
        while (b >= NTILE - ti) { b -= NTILE - ti; ++ti; }
        tj = ti + b;
    } else {
        ti = idx / NTILE;
        tj = idx % NTILE;
    }
    int rowA0 = ti * BM, rowB0 = tj * BM;
    int diag_tile = (sym && ti == tj);

    uint32_t sb = smem_u32(smem);
    const __nv_bfloat16* Abase = Ag + (size_t)rowA0 * CD;
    const __nv_bfloat16* Bbase = Bg + (size_t)rowB0 * CD;

    // loader slots: 1024 cp16 per matrix per chunk, 512 threads -> 2 each
    int lrow = tid >> 3, lch = tid & 7;   // base row 0..63, 16B-chunk 0..7

    // prologue: issue chunks 0 and 1 into stages 0 and 1
#pragma unroll
    for (int s = 0; s < 2; ++s) {
        uint32_t as = sb + s * STG, bs = as + ATILE;
#pragma unroll
        for (int it = 0; it < 2; ++it) {
            int row = lrow + it * 64;
            cp16(as + row * ROWB + lch * 16, Abase + (size_t)row * CD + s * KCH + lch * 8);
            cp16(bs + row * ROWB + lch * 16, Bbase + (size_t)row * CD + s * KCH + lch * 8);
        }
        cp_commit();
    }

    // warp layout: 8x2 grid of 16(M) x 64(N) per warp
    int wm = wid >> 1, wn = wid & 1;
    uint32_t arow = (uint32_t)(wm * 16 + (lane & 15)) * ROWB + ((uint32_t)(lane >> 4) << 4);
    uint32_t brow = (uint32_t)(wn * 64 + (lane & 7) + ((lane >> 4) << 3)) * ROWB
                  + (((uint32_t)(lane >> 3) & 1) << 4);

    float acc[8][4];
#pragma unroll
    for (int j = 0; j < 8; ++j)
#pragma unroll
        for (int e = 0; e < 4; ++e) acc[j][e] = 0.f;

    // 3-stage pipeline, ONE sync per chunk.
#pragma unroll
    for (int c = 0; c < NCHK; ++c) {
        if (c < NCHK - 1) cp_wait1(); else cp_wait0();
        __syncthreads();

        uint32_t abase = sb + (c % NSTG) * STG + arow;
        uint32_t bbase = sb + (c % NSTG) * STG + ATILE + brow;
#pragma unroll
        for (int ks = 0; ks < KCH / 16; ++ks) {
            uint32_t koff = (uint32_t)ks << 5;   // 16 bf16 = 32 bytes
            uint32_t a0[4];
            ldsm4(a0, abase + koff);
#pragma unroll
            for (int ntp = 0; ntp < 4; ++ntp) {
                uint32_t bfr[4];
                ldsm4(bfr, bbase + (uint32_t)(ntp * 16) * ROWB + koff);
                mma_bf16(acc[2 * ntp],     a0, bfr[0], bfr[1]);
                mma_bf16(acc[2 * ntp + 1], a0, bfr[2], bfr[3]);
            }
        }

        if (c + 2 < NCHK) {
            int ch = c + 2;
            uint32_t as = sb + (ch % NSTG) * STG, bs = as + ATILE;
#pragma unroll
            for (int it = 0; it < 2; ++it) {
                int row = lrow + it * 64;
                cp16(as + row * ROWB + lch * 16, Abase + (size_t)row * CD + ch * KCH + lch * 8);
                cp16(bs + row * ROWB + lch * 16, Bbase + (size_t)row * CD + ch * KCH + lch * 8);
            }
            cp_commit();
        }
    }

    // epilogue: nb[k] = -bet[k] * log2(e)
    float nb[5];
#pragma unroll
    for (int k = 0; k < 5; ++k)
        nb[k] = -1.4426950408889634f * (0.5f / __ldg(&sig[k]));

    float part = diag_tile
        ? epilogue<true >(acc, rowA0, rowB0, wm, wn, lane, a2, b2, nb)
        : epilogue<false>(acc, rowA0, rowB0, wm, wn, lane, a2, b2, nb);
    if (sym && ti != tj) part *= 2.0f;

    // warp reduce + cross-warp (16 warps)
#pragma unroll
    for (int o = 16; o > 0; o >>= 1)
        part += __shfl_down_sync(0xFFFFFFFFu, part, o);
    float* sred = (float*)(smem + SM_RED);
    if (lane == 0) sred[wid] = part;
    __syncthreads();
    if (tid == 0) {
        float tot = 0.f;
#pragma unroll
        for (int w = 0; w < 16; ++w) tot += sred[w];
        atomicAdd(&g_acc, weight * (double)tot);
        __threadfence();
        unsigned int ticket = atomicAdd(&g_done, 1u);
        if (ticket == NBLK - 1) {
            g_done = 0;   // replay-safe reset
            // analytic diagonals of xx and yy: each row contributes 5
            out[0] = (float)((g_acc + 2.0 * 5.0 * (double)NR)
                             / ((double)NR * (double)NR));
        }
    }
}

extern "C" void kernel_launch(void* const* d_in, const int* in_sizes, int n_in,
                              void* d_out, int out_size) {
    const float* x   = (const float*)d_in[0];
    const float* y   = (const float*)d_in[1];
    const float* sig = (const float*)d_in[2];
    float* out = (float*)d_out;

    cudaFuncSetAttribute(mmd_mma_kernel,
                         cudaFuncAttributeMaxDynamicSharedMemorySize, SM_TOT);

    mmd_prep_kernel<<<dim3(HWD / 32, CD / 32, 9), dim3(32, 8)>>>(x, y);
    mmd_mma_kernel<<<NBLK, NTHR, SM_TOT>>>(sig, out);
}